// round 15
// baseline (speedup 1.0000x reference)
#include <cuda_runtime.h>
#include <cstdint>

#define NMAX 100000
#define GREC 12            // float4 chunks per node record (48 floats: q,k,v)
#define LPB  32            // loops per block in k_loops (4 threads per loop)

// dynamic smem partition (float4 units). Warp w's q overlays the FIRST HALF of
// warp w's OWN kv region (slots 64w..64w+31): staged, read to regs, overwritten.
#define KV_OFF   0                        // 2048 float4 (32 KB)
#define FCW_OFF  (LPB * 8 * 8)            // 256 float4 (4 KB)
#define IDX_OFF  (FCW_OFF + 256)          // 256 ints (64 float4)
#define FCB_OFF  (IDX_OFF + 64)           // 8 float4 (fco bias)
#define SMEM_BYTES ((FCB_OFF + 8) * 16)   // 38016 B -> 6 blocks/SM (smem-wise)

// Scratch (static __device__ — no runtime allocation)
__device__ float4 g_pre[(size_t)NMAX * GREC];   // per-node: q*(invsqrt8*log2e)[16], k[16], v[16]
__device__ float  g_cpack[576];                 // [0:512) Mt[e][o], [512:544) b32, [544:576) fco_b
__device__ int    g_idx64;                      // 1 if stroke_to_loop is int64

// Constant mirror (warp-uniform immediate-indexed reads: uniform/constant port)
__constant__ __align__(16) float c_pack[576];

// k/v chunk swizzle (8 chunks/slot): key distinct across the 8 loop-groups of a warp
#define SKEY(slot) (((slot) ^ ((slot) >> 3)) & 7)
// q chunk swizzle (4 chunks/slot, 64B slot stride): distinct among same-parity slots
#define QKEY(slot) (((slot) >> 1) & 3)
// fco row swizzle: key distinct over the 4 lanes of a loop group
#define FKEY(o) (((o) >> 3) & 3)

__device__ __forceinline__ int fetch_idx(const void* p, long long i, int is64) {
    if (is64) return (int)__ldg((const long long*)p + i);
    return __ldg((const int*)p + i);
}
__device__ __forceinline__ unsigned long long pk2(float lo, float hi) {
    unsigned long long r;
    asm("mov.b64 %0, {%1, %2};" : "=l"(r) : "f"(lo), "f"(hi));
    return r;
}
__device__ __forceinline__ void upk2(unsigned long long v, float& lo, float& hi) {
    asm("mov.b64 {%0, %1}, %2;" : "=f"(lo), "=f"(hi) : "l"(v));
}
__device__ __forceinline__ void ffma2(unsigned long long& d, unsigned long long a, unsigned long long b) {
    asm("fma.rn.f32x2 %0, %1, %2, %0;" : "+l"(d) : "l"(a), "l"(b));
}
__device__ __forceinline__ void cpa16(uint32_t dst_smem, const void* src) {
    asm volatile("cp.async.cg.shared.global [%0], [%1], 16;" :: "r"(dst_smem), "l"(src));
}
__device__ __forceinline__ float ex2f(float x) {
    float r; asm("ex2.approx.f32 %0, %1;" : "=f"(r) : "f"(x)); return r;
}
__device__ __forceinline__ float rcpf(float x) {
    float r; asm("rcp.approx.f32 %0, %1;" : "=f"(r) : "f"(x)); return r;
}

// ---------------- Kernel 1: per-node precompute (+ fused prep in block 0) ----------------
// 256 threads/block: weight staging amortized over 2x nodes vs 128.
__global__ void __launch_bounds__(256)
k_node(const float* __restrict__ nf,
       const float* __restrict__ w1, const float* __restrict__ b1,
       const float* __restrict__ w2, const float* __restrict__ b2,
       const float* __restrict__ wp, const float* __restrict__ bp,
       const float* __restrict__ fc_w, const float* __restrict__ opw,
       const float* __restrict__ opb, const float* __restrict__ fc_b,
       const float* __restrict__ fco_b,
       const int* __restrict__ idx_raw, int N) {
    __shared__ __align__(16) float s_w1[256];    // [32][8] padded rows
    __shared__ __align__(16) float s_w2t[512];   // transposed-interleaved: [j][e]
    __shared__ __align__(16) float s_wpt[768];   // transposed-interleaved: [e][o]
    __shared__ __align__(16) float s_b2[16];
    __shared__ __align__(16) float s_bp[48];
    __shared__ float s_b1[32];
    __shared__ int s_flag;

    const int tid = threadIdx.x;

    if (blockIdx.x == 0) {
        if (tid == 0) s_flag = 0;
        #pragma unroll
        for (int i = tid; i < 512; i += 256) {
            int o = i >> 4, e = i & 15;
            float acc = 0.f;
            #pragma unroll
            for (int j = 0; j < 16; j++) acc += __ldg(fc_w + o * 16 + j) * __ldg(opw + j * 16 + e);
            g_cpack[e * 32 + o] = acc;     // Mt[e][o]
        }
        if (tid < 32) {
            float acc = __ldg(fc_b + tid);
            #pragma unroll
            for (int j = 0; j < 16; j++) acc += __ldg(fc_w + tid * 16 + j) * __ldg(opb + j);
            g_cpack[512 + tid] = acc;
        }
        if (tid >= 32 && tid < 64) g_cpack[544 + (tid - 32)] = __ldg(fco_b + (tid - 32));
        __syncthreads();
        if (tid < 128 && __ldg(idx_raw + 2 * tid + 1) != 0) atomicOr(&s_flag, 1);
        __syncthreads();
        if (tid == 0) g_idx64 = (s_flag == 0) ? 1 : 0;
    }

    // ---- stage weights (transposed-interleaved for packed math) ----
    for (int i = tid; i < 256; i += 256) {
        int o = i >> 3, c = i & 7;
        s_w1[i] = (c < 6) ? __ldg(w1 + o * 6 + c) : 0.f;
    }
    #pragma unroll
    for (int i = tid; i < 512; i += 256) {       // s_w2t[j*16+e] = w2[e*32+j]
        int j = i >> 4, e = i & 15;
        s_w2t[i] = __ldg(w2 + e * 32 + j);
    }
    #pragma unroll
    for (int i = tid; i < 768; i += 256) {       // s_wpt[e*48+o] = wp[o*16+e]
        int e = i / 48, o = i - e * 48;
        s_wpt[i] = __ldg(wp + o * 16 + e);
    }
    if (tid < 32) s_b1[tid] = __ldg(b1 + tid);
    if (tid >= 32 && tid < 48) s_b2[tid - 32] = __ldg(b2 + (tid - 32));
    if (tid >= 64 && tid < 112) s_bp[tid - 64] = __ldg(bp + (tid - 64));
    __syncthreads();

    int n = blockIdx.x * 256 + tid;
    if (n >= N) return;

    float f[6];
    #pragma unroll
    for (int i = 0; i < 6; i++) f[i] = __ldg(nf + (size_t)n * 6 + i);

    const float4* w1v = (const float4*)s_w1;
    float h[32];
    #pragma unroll
    for (int o = 0; o < 32; o++) {
        float4 a = w1v[o * 2], b = w1v[o * 2 + 1];
        float acc = s_b1[o] + a.x * f[0] + a.y * f[1] + a.z * f[2] + a.w * f[3]
                  + b.x * f[4] + b.y * f[5];
        h[o] = fmaxf(acc, 0.f);
    }

    // fc2 packed: X2[p] = (x[2p], x[2p+1])
    const ulonglong2* w2t2 = (const ulonglong2*)s_w2t;
    unsigned long long X2[8];
    {
        const unsigned long long* b2u = (const unsigned long long*)s_b2;
        #pragma unroll
        for (int p = 0; p < 8; p++) X2[p] = b2u[p];
    }
    #pragma unroll
    for (int j = 0; j < 32; j++) {
        unsigned long long hh = pk2(h[j], h[j]);
        #pragma unroll
        for (int t = 0; t < 4; t++) {
            ulonglong2 wv = w2t2[j * 4 + t];
            ffma2(X2[2 * t], hh, wv.x);
            ffma2(X2[2 * t + 1], hh, wv.y);
        }
    }
    float x[16];
    #pragma unroll
    for (int p = 0; p < 8; p++) upk2(X2[p], x[2 * p], x[2 * p + 1]);

    // in_proj packed: Q2[o2] = (qkv[2o2], qkv[2o2+1])
    const ulonglong2* wpt2 = (const ulonglong2*)s_wpt;
    unsigned long long Q2[24];
    {
        const unsigned long long* bpu = (const unsigned long long*)s_bp;
        #pragma unroll
        for (int o2 = 0; o2 < 24; o2++) Q2[o2] = bpu[o2];
    }
    #pragma unroll
    for (int e = 0; e < 16; e++) {
        unsigned long long xx = pk2(x[e], x[e]);
        #pragma unroll
        for (int t = 0; t < 12; t++) {
            ulonglong2 wv = wpt2[e * 12 + t];
            ffma2(Q2[2 * t], xx, wv.x);
            ffma2(Q2[2 * t + 1], xx, wv.y);
        }
    }
    float qkv[48];
    #pragma unroll
    for (int o2 = 0; o2 < 24; o2++) upk2(Q2[o2], qkv[2 * o2], qkv[2 * o2 + 1]);

    float4* rec4 = g_pre + (size_t)n * GREC;
    // 1/sqrt(8) * log2(e): folds score scale AND exp2 conversion into q
    const float s = 0.35355339059327373f * 1.4426950408889634f;
    #pragma unroll
    for (int j = 0; j < 4; j++)
        rec4[j] = make_float4(qkv[4 * j] * s, qkv[4 * j + 1] * s, qkv[4 * j + 2] * s, qkv[4 * j + 3] * s);
    #pragma unroll
    for (int j = 0; j < 8; j++)
        rec4[4 + j] = make_float4(qkv[16 + 4 * j], qkv[17 + 4 * j], qkv[18 + 4 * j], qkv[19 + 4 * j]);
}

// ---------------- Kernel 2: per-loop attention + epilogue ----------------
// 32 loops/block, 4 threads/loop, query rows {lj, lj+4}/thread.
// Warp-local staging; warp w's q staged into warp w's OWN kv region (race-free),
// read to regs, then overwritten by warp w's kv staging. 6 blocks/SM target.
__global__ void __launch_bounds__(128, 6)
k_loops(const void* __restrict__ s2l,
        const float* __restrict__ fco_w, const float* __restrict__ fco_b,
        float* __restrict__ out, int B) {
    extern __shared__ __align__(16) float4 smem[];
    float4* s_kv  = smem + KV_OFF;
    float4* s_fcw = smem + FCW_OFF;
    int*    s_idx = reinterpret_cast<int*>(smem + IDX_OFF);
    float4* s_fcb4 = smem + FCB_OFF;

    const int tid = threadIdx.x;
    const int wid = tid >> 5;
    const int lane = tid & 31;
    const int wslot0 = wid * 64;               // this warp's first slot
    float4* s_qw = s_kv + wslot0 * 8;          // warp-private q overlay (within OWN kv region)
    const long long base8 = (long long)blockIdx.x * (LPB * 8);
    const long long total8 = (long long)B * 8;
    const int is64 = g_idx64;

    // ---- phase A (block-wide, single barrier): fco weights + bias ----
    const float4* fcw4 = (const float4*)fco_w;
    #pragma unroll
    for (int i = tid; i < 256; i += 128) {
        int r = i >> 3, k4 = i & 7;
        s_fcw[r * 8 + (k4 ^ FKEY(r))] = __ldg(fcw4 + i);
    }
    if (tid < 8) s_fcb4[tid] = __ldg((const float4*)fco_b + tid);
    __syncthreads();

    // ---- warp-local: indices for this warp's 64 slots ----
    #pragma unroll
    for (int i = 0; i < 2; i++) {
        int slot = wslot0 + lane + i * 32;
        long long gi = base8 + slot;
        if (gi >= total8) gi = 0;
        s_idx[slot] = fetch_idx(s2l, gi, is64);
    }
    __syncwarp();

    // ---- stage q (coalesced chunk-major cp.async) into WARP-OWN overlay ----
    {
        const int c4 = lane & 3, g4 = lane >> 2;
        #pragma unroll
        for (int it = 0; it < 8; it++) {
            int ls = it * 8 + g4;              // local slot 0..63
            int node = s_idx[wslot0 + ls];
            uint32_t dst = (uint32_t)__cvta_generic_to_shared(&s_qw[ls * 4 + (c4 ^ QKEY(ls))]);
            cpa16(dst, g_pre + (size_t)node * GREC + c4);
        }
        asm volatile("cp.async.commit_group;");
        asm volatile("cp.async.wait_group 0;");
    }
    __syncwarp();

    const int ll = tid >> 2;       // loop within block (warp covers 8 loops)
    const int lj = tid & 3;        // lane within loop; query rows lj and lj+4
    const int slotA = ll * 8 + lj;
    const int slotB = slotA + 4;
    const int lsA = slotA & 63;    // local slot within warp
    const int lsB = slotB & 63;

    // ---- read own q rows into registers (conflict-free via QKEY) ----
    unsigned long long q2A[8], q2B[8];
    {
        const ulonglong2* sq = reinterpret_cast<const ulonglong2*>(s_qw);
        int ka = QKEY(lsA);
        #pragma unroll
        for (int j = 0; j < 4; j++) {
            ulonglong2 v = sq[lsA * 4 + (j ^ ka)];
            q2A[2 * j] = v.x; q2A[2 * j + 1] = v.y;
        }
        int kb = QKEY(lsB);
        #pragma unroll
        for (int j = 0; j < 4; j++) {
            ulonglong2 v = sq[lsB * 4 + (j ^ kb)];
            q2B[2 * j] = v.x; q2B[2 * j + 1] = v.y;
        }
    }
    // force all q LDS results into registers before the region is overwritten
    asm volatile("" : "+l"(q2A[0]), "+l"(q2A[1]), "+l"(q2A[2]), "+l"(q2A[3]),
                      "+l"(q2A[4]), "+l"(q2A[5]), "+l"(q2A[6]), "+l"(q2A[7]),
                      "+l"(q2B[0]), "+l"(q2B[1]), "+l"(q2B[2]), "+l"(q2B[3]),
                      "+l"(q2B[4]), "+l"(q2B[5]), "+l"(q2B[6]), "+l"(q2B[7]) :: "memory");
    __syncwarp();

    // ---- stage kv for this warp's 64 slots (overwrites the q overlay safely) ----
    {
        const int c8 = lane & 7, g = lane >> 3;
        #pragma unroll
        for (int it = 0; it < 16; it++) {
            int slot = wslot0 + it * 4 + g;
            int node = s_idx[slot];
            uint32_t dst = (uint32_t)__cvta_generic_to_shared(&s_kv[slot * 8 + (c8 ^ SKEY(slot))]);
            cpa16(dst, g_pre + (size_t)node * GREC + 4 + c8);
        }
        asm volatile("cp.async.commit_group;");
        asm volatile("cp.async.wait_group 0;");
    }
    __syncwarp();

    const ulonglong2* su = reinterpret_cast<const ulonglong2*>(s_kv);

    // ---- scores (log2-scaled; both heads, both rows); k tiles shared across rows ----
    float p0A[8], p1A[8], p0B[8], p1B[8];
    #pragma unroll
    for (int m = 0; m < 8; m++) {
        int sm = ll * 8 + m;
        int key = SKEY(sm);
        int base = sm * 8;
        ulonglong2 k0 = su[base + (0 ^ key)];
        ulonglong2 k1 = su[base + (1 ^ key)];
        ulonglong2 k2 = su[base + (2 ^ key)];
        ulonglong2 k3 = su[base + (3 ^ key)];
        unsigned long long a0 = 0ULL, a1 = 0ULL, b0 = 0ULL, b1 = 0ULL;
        ffma2(a0, q2A[0], k0.x); ffma2(a0, q2A[1], k0.y);
        ffma2(a0, q2A[2], k1.x); ffma2(a0, q2A[3], k1.y);
        ffma2(a1, q2A[4], k2.x); ffma2(a1, q2A[5], k2.y);
        ffma2(a1, q2A[6], k3.x); ffma2(a1, q2A[7], k3.y);
        ffma2(b0, q2B[0], k0.x); ffma2(b0, q2B[1], k0.y);
        ffma2(b0, q2B[2], k1.x); ffma2(b0, q2B[3], k1.y);
        ffma2(b1, q2B[4], k2.x); ffma2(b1, q2B[5], k2.y);
        ffma2(b1, q2B[6], k3.x); ffma2(b1, q2B[7], k3.y);
        float lo, hi;
        upk2(a0, lo, hi); p0A[m] = lo + hi;
        upk2(a1, lo, hi); p1A[m] = lo + hi;
        upk2(b0, lo, hi); p0B[m] = lo + hi;
        upk2(b1, lo, hi); p1B[m] = lo + hi;
    }

    // ---- softmax over m, per head, per row (base-2 domain) ----
    {
        float mx0 = p0A[0], mx1 = p1A[0], mx2 = p0B[0], mx3 = p1B[0];
        #pragma unroll
        for (int m = 1; m < 8; m++) {
            mx0 = fmaxf(mx0, p0A[m]); mx1 = fmaxf(mx1, p1A[m]);
            mx2 = fmaxf(mx2, p0B[m]); mx3 = fmaxf(mx3, p1B[m]);
        }
        float s0 = 0.f, s1 = 0.f, s2 = 0.f, s3 = 0.f;
        #pragma unroll
        for (int m = 0; m < 8; m++) {
            p0A[m] = ex2f(p0A[m] - mx0); s0 += p0A[m];
            p1A[m] = ex2f(p1A[m] - mx1); s1 += p1A[m];
            p0B[m] = ex2f(p0B[m] - mx2); s2 += p0B[m];
            p1B[m] = ex2f(p1B[m] - mx3); s3 += p1B[m];
        }
        float i0 = rcpf(s0), i1 = rcpf(s1), i2 = rcpf(s2), i3 = rcpf(s3);
        #pragma unroll
        for (int m = 0; m < 8; m++) {
            p0A[m] *= i0; p1A[m] *= i1; p0B[m] *= i2; p1B[m] *= i3;
        }
    }

    // ---- ctx for both rows; v tiles shared ----
    unsigned long long cxA[8], cxB[8];
    #pragma unroll
    for (int j = 0; j < 8; j++) { cxA[j] = 0ULL; cxB[j] = 0ULL; }
    #pragma unroll
    for (int m = 0; m < 8; m++) {
        int sm = ll * 8 + m;
        int key = SKEY(sm);
        int base = sm * 8;
        ulonglong2 v0 = su[base + (4 ^ key)];
        ulonglong2 v1 = su[base + (5 ^ key)];
        ulonglong2 v2 = su[base + (6 ^ key)];
        ulonglong2 v3 = su[base + (7 ^ key)];
        unsigned long long ppA0 = pk2(p0A[m], p0A[m]);
        unsigned long long ppA1 = pk2(p1A[m], p1A[m]);
        unsigned long long ppB0 = pk2(p0B[m], p0B[m]);
        unsigned long long ppB1 = pk2(p1B[m], p1B[m]);
        ffma2(cxA[0], ppA0, v0.x); ffma2(cxA[1], ppA0, v0.y);
        ffma2(cxA[2], ppA0, v1.x); ffma2(cxA[3], ppA0, v1.y);
        ffma2(cxA[4], ppA1, v2.x); ffma2(cxA[5], ppA1, v2.y);
        ffma2(cxA[6], ppA1, v3.x); ffma2(cxA[7], ppA1, v3.y);
        ffma2(cxB[0], ppB0, v0.x); ffma2(cxB[1], ppB0, v0.y);
        ffma2(cxB[2], ppB0, v1.x); ffma2(cxB[3], ppB0, v1.y);
        ffma2(cxB[4], ppB1, v2.x); ffma2(cxB[5], ppB1, v2.y);
        ffma2(cxB[6], ppB1, v3.x); ffma2(cxB[7], ppB1, v3.y);
    }
    float ceA[16], ceB[16];
    #pragma unroll
    for (int j = 0; j < 8; j++) {
        upk2(cxA[j], ceA[2 * j], ceA[2 * j + 1]);
        upk2(cxB[j], ceB[2 * j], ceB[2 * j + 1]);
    }

    // ---- z = Mt^T ctx, constant port via 128-bit LDCU; bias as accumulator init ----
    const ulonglong2* cMv = reinterpret_cast<const ulonglong2*>(c_pack);
    const unsigned long long* cBu = reinterpret_cast<const unsigned long long*>(c_pack + 512);
    float t[32];
    #pragma unroll
    for (int pass = 0; pass < 2; pass++) {
        unsigned long long zA[8], zB[8];
        #pragma unroll
        for (int j = 0; j < 8; j++) {
            unsigned long long bb = cBu[pass * 8 + j];
            zA[j] = bb; zB[j] = bb;
        }
        #pragma unroll
        for (int e = 0; e < 16; e++) {
            unsigned long long pceA = pk2(ceA[e], ceA[e]);
            unsigned long long pceB = pk2(ceB[e], ceB[e]);
            #pragma unroll
            for (int j4 = 0; j4 < 4; j4++) {
                ulonglong2 wv = cMv[e * 8 + pass * 4 + j4];   // 128-bit constant load
                ffma2(zA[2 * j4], pceA, wv.x);
                ffma2(zA[2 * j4 + 1], pceA, wv.y);
                ffma2(zB[2 * j4], pceB, wv.x);
                ffma2(zB[2 * j4 + 1], pceB, wv.y);
            }
        }
        #pragma unroll
        for (int j = 0; j < 8; j++) {
            float la, ha, lb, hb;
            upk2(zA[j], la, ha);
            upk2(zB[j], lb, hb);
            t[pass * 16 + 2 * j]     = fmaxf(la, 0.f) + fmaxf(lb, 0.f);
            t[pass * 16 + 2 * j + 1] = fmaxf(ha, 0.f) + fmaxf(hb, 0.f);
        }
    }

    // ---- butterfly-sum over the 4 lanes of the loop group; mean ----
    #pragma unroll
    for (int st = 0; st < 2; st++) {
        int mask = 1 << st;
        #pragma unroll
        for (int o = 0; o < 32; o++) t[o] += __shfl_xor_sync(0xffffffffu, t[o], mask);
    }
    unsigned long long t2[16];
    #pragma unroll
    for (int j = 0; j < 16; j++) t2[j] = pk2(t[2 * j] * 0.125f, t[2 * j + 1] * 0.125f);

    // ---- fco: each of 4 lanes computes 8 outputs (packed, swizzled smem) ----
    const ulonglong2* sf = reinterpret_cast<const ulonglong2*>(s_fcw);
    float4 fa = s_fcb4[lj * 2], fb = s_fcb4[lj * 2 + 1];
    float fcb[8] = {fa.x, fa.y, fa.z, fa.w, fb.x, fb.y, fb.z, fb.w};
    float r[8];
    #pragma unroll
    for (int jj = 0; jj < 8; jj++) {
        int o2 = lj * 8 + jj;
        int key = FKEY(o2);
        unsigned long long acc = 0ULL;
        #pragma unroll
        for (int k4 = 0; k4 < 8; k4++) {
            ulonglong2 wv = sf[o2 * 8 + (k4 ^ key)];
            ffma2(acc, t2[2 * k4], wv.x);
            ffma2(acc, t2[2 * k4 + 1], wv.y);
        }
        float lo, hi;
        upk2(acc, lo, hi);
        r[jj] = lo + hi + fcb[jj];
    }

    long long lg = (long long)blockIdx.x * LPB + ll;
    if (lg < B) {
        float4* o4 = reinterpret_cast<float4*>(out);
        o4[lg * 8 + lj * 2]     = make_float4(r[0], r[1], r[2], r[3]);
        o4[lg * 8 + lj * 2 + 1] = make_float4(r[4], r[5], r[6], r[7]);
    }
}

// ---------------- launch ----------------
extern "C" void kernel_launch(void* const* d_in, const int* in_sizes, int n_in,
                              void* d_out, int out_size) {
    const float* node_features = (const float*)d_in[0];
    const void*  stroke_to_loop = d_in[1];
    const float* fc1_w = (const float*)d_in[2];
    const float* fc1_b = (const float*)d_in[3];
    const float* fc2_w = (const float*)d_in[4];
    const float* fc2_b = (const float*)d_in[5];
    const float* in_proj_w = (const float*)d_in[6];
    const float* in_proj_b = (const float*)d_in[7];
    const float* out_proj_w = (const float*)d_in[8];
    const float* out_proj_b = (const float*)d_in[9];
    const float* fc_w = (const float*)d_in[10];
    const float* fc_b = (const float*)d_in[11];
    const float* fco_w = (const float*)d_in[12];
    const float* fco_b = (const float*)d_in[13];

    int N = in_sizes[0] / 6;
    int B = in_sizes[1] / 8;

    cudaFuncSetAttribute(k_loops, cudaFuncAttributeMaxDynamicSharedMemorySize, SMEM_BYTES);

    k_node<<<(N + 255) / 256, 256>>>(node_features, fc1_w, fc1_b, fc2_w, fc2_b,
                                     in_proj_w, in_proj_b,
                                     fc_w, out_proj_w, out_proj_b, fc_b, fco_b,
                                     (const int*)stroke_to_loop, N);

    // single stream-ordered D2D copy of all folded constants
    void* gp = nullptr;
    cudaGetSymbolAddress(&gp, g_cpack);
    cudaMemcpyToSymbolAsync(c_pack, gp, 576 * sizeof(float), 0,
                            cudaMemcpyDeviceToDevice, 0);

    k_loops<<<(B + LPB - 1) / LPB, 128, SMEM_BYTES>>>(stroke_to_loop, fco_w, fco_b,
                                                      (float*)d_out, B);
}

// round 16
// speedup vs baseline: 1.0439x; 1.0439x over previous
#include <cuda_runtime.h>
#include <cstdint>

#define NMAX 100000
#define GREC 12            // float4 chunks per node record (48 floats: q,k,v)
#define LPB  32            // loops per block in k_loops (4 threads per loop)

// dynamic smem partition (float4 units). Warp w's q overlays the FIRST HALF of
// warp w's OWN kv region (slots 64w..64w+31): staged, read to regs, overwritten.
#define KV_OFF   0                        // 2048 float4 (32 KB)
#define FCW_OFF  (LPB * 8 * 8)            // 256 float4 (4 KB)
#define IDX_OFF  (FCW_OFF + 256)          // 256 ints (64 float4)
#define FCB_OFF  (IDX_OFF + 64)           // 8 float4 (fco bias)
#define SMEM_BYTES ((FCB_OFF + 8) * 16)   // 38016 B -> 5 blocks/SM

// Scratch (static __device__ — no runtime allocation)
__device__ float4 g_pre[(size_t)NMAX * GREC];   // per-node: q*(invsqrt8*log2e)[16], k[16], v[16]
__device__ float  g_cpack[576];                 // [0:512) Mt[e][o], [512:544) b32, [544:576) fco_b
__device__ int    g_idx64;                      // 1 if stroke_to_loop is int64

// Constant mirror (warp-uniform immediate-indexed reads: uniform/constant port)
__constant__ __align__(16) float c_pack[576];

// k/v chunk swizzle (8 chunks/slot): key distinct across the 8 loop-groups of a warp
#define SKEY(slot) (((slot) ^ ((slot) >> 3)) & 7)
// q chunk swizzle (4 chunks/slot, 64B slot stride): distinct among same-parity slots
#define QKEY(slot) (((slot) >> 1) & 3)
// fco row swizzle: key distinct over the 4 lanes of a loop group
#define FKEY(o) (((o) >> 3) & 3)

__device__ __forceinline__ int fetch_idx(const void* p, long long i, int is64) {
    if (is64) return (int)__ldg((const long long*)p + i);
    return __ldg((const int*)p + i);
}
__device__ __forceinline__ unsigned long long pk2(float lo, float hi) {
    unsigned long long r;
    asm("mov.b64 %0, {%1, %2};" : "=l"(r) : "f"(lo), "f"(hi));
    return r;
}
__device__ __forceinline__ void upk2(unsigned long long v, float& lo, float& hi) {
    asm("mov.b64 {%0, %1}, %2;" : "=f"(lo), "=f"(hi) : "l"(v));
}
__device__ __forceinline__ void ffma2(unsigned long long& d, unsigned long long a, unsigned long long b) {
    asm("fma.rn.f32x2 %0, %1, %2, %0;" : "+l"(d) : "l"(a), "l"(b));
}
__device__ __forceinline__ void cpa16(uint32_t dst_smem, const void* src) {
    asm volatile("cp.async.cg.shared.global [%0], [%1], 16;" :: "r"(dst_smem), "l"(src));
}
__device__ __forceinline__ float ex2f(float x) {
    float r; asm("ex2.approx.f32 %0, %1;" : "=f"(r) : "f"(x)); return r;
}
__device__ __forceinline__ float rcpf(float x) {
    float r; asm("rcp.approx.f32 %0, %1;" : "=f"(r) : "f"(x)); return r;
}

// ---------------- Kernel 1: per-node precompute (+ fused prep in block 0) ----------------
// 256 threads/block: weight staging amortized over 2x nodes vs 128.
__global__ void __launch_bounds__(256)
k_node(const float* __restrict__ nf,
       const float* __restrict__ w1, const float* __restrict__ b1,
       const float* __restrict__ w2, const float* __restrict__ b2,
       const float* __restrict__ wp, const float* __restrict__ bp,
       const float* __restrict__ fc_w, const float* __restrict__ opw,
       const float* __restrict__ opb, const float* __restrict__ fc_b,
       const float* __restrict__ fco_b,
       const int* __restrict__ idx_raw, int N) {
    __shared__ __align__(16) float s_w1[256];    // [32][8] padded rows
    __shared__ __align__(16) float s_w2t[512];   // transposed-interleaved: [j][e]
    __shared__ __align__(16) float s_wpt[768];   // transposed-interleaved: [e][o]
    __shared__ __align__(16) float s_b2[16];
    __shared__ __align__(16) float s_bp[48];
    __shared__ float s_b1[32];
    __shared__ int s_flag;

    const int tid = threadIdx.x;

    if (blockIdx.x == 0) {
        if (tid == 0) s_flag = 0;
        #pragma unroll
        for (int i = tid; i < 512; i += 256) {
            int o = i >> 4, e = i & 15;
            float acc = 0.f;
            #pragma unroll
            for (int j = 0; j < 16; j++) acc += __ldg(fc_w + o * 16 + j) * __ldg(opw + j * 16 + e);
            g_cpack[e * 32 + o] = acc;     // Mt[e][o]
        }
        if (tid < 32) {
            float acc = __ldg(fc_b + tid);
            #pragma unroll
            for (int j = 0; j < 16; j++) acc += __ldg(fc_w + tid * 16 + j) * __ldg(opb + j);
            g_cpack[512 + tid] = acc;
        }
        if (tid >= 32 && tid < 64) g_cpack[544 + (tid - 32)] = __ldg(fco_b + (tid - 32));
        __syncthreads();
        if (tid < 128 && __ldg(idx_raw + 2 * tid + 1) != 0) atomicOr(&s_flag, 1);
        __syncthreads();
        if (tid == 0) g_idx64 = (s_flag == 0) ? 1 : 0;
    }

    // ---- stage weights (transposed-interleaved for packed math) ----
    for (int i = tid; i < 256; i += 256) {
        int o = i >> 3, c = i & 7;
        s_w1[i] = (c < 6) ? __ldg(w1 + o * 6 + c) : 0.f;
    }
    #pragma unroll
    for (int i = tid; i < 512; i += 256) {       // s_w2t[j*16+e] = w2[e*32+j]
        int j = i >> 4, e = i & 15;
        s_w2t[i] = __ldg(w2 + e * 32 + j);
    }
    #pragma unroll
    for (int i = tid; i < 768; i += 256) {       // s_wpt[e*48+o] = wp[o*16+e]
        int e = i / 48, o = i - e * 48;
        s_wpt[i] = __ldg(wp + o * 16 + e);
    }
    if (tid < 32) s_b1[tid] = __ldg(b1 + tid);
    if (tid >= 32 && tid < 48) s_b2[tid - 32] = __ldg(b2 + (tid - 32));
    if (tid >= 64 && tid < 112) s_bp[tid - 64] = __ldg(bp + (tid - 64));
    __syncthreads();

    int n = blockIdx.x * 256 + tid;
    if (n >= N) return;

    float f[6];
    #pragma unroll
    for (int i = 0; i < 6; i++) f[i] = __ldg(nf + (size_t)n * 6 + i);

    const float4* w1v = (const float4*)s_w1;
    float h[32];
    #pragma unroll
    for (int o = 0; o < 32; o++) {
        float4 a = w1v[o * 2], b = w1v[o * 2 + 1];
        float acc = s_b1[o] + a.x * f[0] + a.y * f[1] + a.z * f[2] + a.w * f[3]
                  + b.x * f[4] + b.y * f[5];
        h[o] = fmaxf(acc, 0.f);
    }

    // fc2 packed: X2[p] = (x[2p], x[2p+1])
    const ulonglong2* w2t2 = (const ulonglong2*)s_w2t;
    unsigned long long X2[8];
    {
        const unsigned long long* b2u = (const unsigned long long*)s_b2;
        #pragma unroll
        for (int p = 0; p < 8; p++) X2[p] = b2u[p];
    }
    #pragma unroll
    for (int j = 0; j < 32; j++) {
        unsigned long long hh = pk2(h[j], h[j]);
        #pragma unroll
        for (int t = 0; t < 4; t++) {
            ulonglong2 wv = w2t2[j * 4 + t];
            ffma2(X2[2 * t], hh, wv.x);
            ffma2(X2[2 * t + 1], hh, wv.y);
        }
    }
    float x[16];
    #pragma unroll
    for (int p = 0; p < 8; p++) upk2(X2[p], x[2 * p], x[2 * p + 1]);

    // in_proj packed: Q2[o2] = (qkv[2o2], qkv[2o2+1])
    const ulonglong2* wpt2 = (const ulonglong2*)s_wpt;
    unsigned long long Q2[24];
    {
        const unsigned long long* bpu = (const unsigned long long*)s_bp;
        #pragma unroll
        for (int o2 = 0; o2 < 24; o2++) Q2[o2] = bpu[o2];
    }
    #pragma unroll
    for (int e = 0; e < 16; e++) {
        unsigned long long xx = pk2(x[e], x[e]);
        #pragma unroll
        for (int t = 0; t < 12; t++) {
            ulonglong2 wv = wpt2[e * 12 + t];
            ffma2(Q2[2 * t], xx, wv.x);
            ffma2(Q2[2 * t + 1], xx, wv.y);
        }
    }
    float qkv[48];
    #pragma unroll
    for (int o2 = 0; o2 < 24; o2++) upk2(Q2[o2], qkv[2 * o2], qkv[2 * o2 + 1]);

    float4* rec4 = g_pre + (size_t)n * GREC;
    // 1/sqrt(8) * log2(e): folds score scale AND exp2 conversion into q
    const float s = 0.35355339059327373f * 1.4426950408889634f;
    #pragma unroll
    for (int j = 0; j < 4; j++)
        rec4[j] = make_float4(qkv[4 * j] * s, qkv[4 * j + 1] * s, qkv[4 * j + 2] * s, qkv[4 * j + 3] * s);
    #pragma unroll
    for (int j = 0; j < 8; j++)
        rec4[4 + j] = make_float4(qkv[16 + 4 * j], qkv[17 + 4 * j], qkv[18 + 4 * j], qkv[19 + 4 * j]);
}

// ---------------- Kernel 2: per-loop attention + epilogue ----------------
// 32 loops/block, 4 threads/loop, query rows {lj, lj+4}/thread.
// Warp-local staging; warp w's q staged into warp w's OWN kv region (race-free),
// read to regs, then overwritten by warp w's kv staging. 5 blocks/SM (proven optimum).
__global__ void __launch_bounds__(128, 5)
k_loops(const void* __restrict__ s2l,
        const float* __restrict__ fco_w, const float* __restrict__ fco_b,
        float* __restrict__ out, int B) {
    extern __shared__ __align__(16) float4 smem[];
    float4* s_kv  = smem + KV_OFF;
    float4* s_fcw = smem + FCW_OFF;
    int*    s_idx = reinterpret_cast<int*>(smem + IDX_OFF);
    float4* s_fcb4 = smem + FCB_OFF;

    const int tid = threadIdx.x;
    const int wid = tid >> 5;
    const int lane = tid & 31;
    const int wslot0 = wid * 64;               // this warp's first slot
    float4* s_qw = s_kv + wslot0 * 8;          // warp-private q overlay (within OWN kv region)
    const long long base8 = (long long)blockIdx.x * (LPB * 8);
    const long long total8 = (long long)B * 8;
    const int is64 = g_idx64;

    // ---- phase A (block-wide, single barrier): fco weights + bias ----
    const float4* fcw4 = (const float4*)fco_w;
    #pragma unroll
    for (int i = tid; i < 256; i += 128) {
        int r = i >> 3, k4 = i & 7;
        s_fcw[r * 8 + (k4 ^ FKEY(r))] = __ldg(fcw4 + i);
    }
    if (tid < 8) s_fcb4[tid] = __ldg((const float4*)fco_b + tid);
    __syncthreads();

    // ---- warp-local: indices for this warp's 64 slots ----
    #pragma unroll
    for (int i = 0; i < 2; i++) {
        int slot = wslot0 + lane + i * 32;
        long long gi = base8 + slot;
        if (gi >= total8) gi = 0;
        s_idx[slot] = fetch_idx(s2l, gi, is64);
    }
    __syncwarp();

    // ---- stage q (coalesced chunk-major cp.async) into WARP-OWN overlay ----
    {
        const int c4 = lane & 3, g4 = lane >> 2;
        #pragma unroll
        for (int it = 0; it < 8; it++) {
            int ls = it * 8 + g4;              // local slot 0..63
            int node = s_idx[wslot0 + ls];
            uint32_t dst = (uint32_t)__cvta_generic_to_shared(&s_qw[ls * 4 + (c4 ^ QKEY(ls))]);
            cpa16(dst, g_pre + (size_t)node * GREC + c4);
        }
        asm volatile("cp.async.commit_group;");
        asm volatile("cp.async.wait_group 0;");
    }
    __syncwarp();

    const int ll = tid >> 2;       // loop within block (warp covers 8 loops)
    const int lj = tid & 3;        // lane within loop; query rows lj and lj+4
    const int slotA = ll * 8 + lj;
    const int slotB = slotA + 4;
    const int lsA = slotA & 63;    // local slot within warp
    const int lsB = slotB & 63;

    // ---- read own q rows into registers (conflict-free via QKEY) ----
    unsigned long long q2A[8], q2B[8];
    {
        const ulonglong2* sq = reinterpret_cast<const ulonglong2*>(s_qw);
        int ka = QKEY(lsA);
        #pragma unroll
        for (int j = 0; j < 4; j++) {
            ulonglong2 v = sq[lsA * 4 + (j ^ ka)];
            q2A[2 * j] = v.x; q2A[2 * j + 1] = v.y;
        }
        int kb = QKEY(lsB);
        #pragma unroll
        for (int j = 0; j < 4; j++) {
            ulonglong2 v = sq[lsB * 4 + (j ^ kb)];
            q2B[2 * j] = v.x; q2B[2 * j + 1] = v.y;
        }
    }
    // force all q LDS results into registers before the region is overwritten
    asm volatile("" : "+l"(q2A[0]), "+l"(q2A[1]), "+l"(q2A[2]), "+l"(q2A[3]),
                      "+l"(q2A[4]), "+l"(q2A[5]), "+l"(q2A[6]), "+l"(q2A[7]),
                      "+l"(q2B[0]), "+l"(q2B[1]), "+l"(q2B[2]), "+l"(q2B[3]),
                      "+l"(q2B[4]), "+l"(q2B[5]), "+l"(q2B[6]), "+l"(q2B[7]) :: "memory");
    __syncwarp();

    // ---- stage kv for this warp's 64 slots (overwrites the q overlay safely) ----
    {
        const int c8 = lane & 7, g = lane >> 3;
        #pragma unroll
        for (int it = 0; it < 16; it++) {
            int slot = wslot0 + it * 4 + g;
            int node = s_idx[slot];
            uint32_t dst = (uint32_t)__cvta_generic_to_shared(&s_kv[slot * 8 + (c8 ^ SKEY(slot))]);
            cpa16(dst, g_pre + (size_t)node * GREC + 4 + c8);
        }
        asm volatile("cp.async.commit_group;");
        asm volatile("cp.async.wait_group 0;");
    }
    __syncwarp();

    const ulonglong2* su = reinterpret_cast<const ulonglong2*>(s_kv);

    // ---- scores (log2-scaled; both heads, both rows); k tiles shared across rows ----
    float p0A[8], p1A[8], p0B[8], p1B[8];
    #pragma unroll
    for (int m = 0; m < 8; m++) {
        int sm = ll * 8 + m;
        int key = SKEY(sm);
        int base = sm * 8;
        ulonglong2 k0 = su[base + (0 ^ key)];
        ulonglong2 k1 = su[base + (1 ^ key)];
        ulonglong2 k2 = su[base + (2 ^ key)];
        ulonglong2 k3 = su[base + (3 ^ key)];
        unsigned long long a0 = 0ULL, a1 = 0ULL, b0 = 0ULL, b1 = 0ULL;
        ffma2(a0, q2A[0], k0.x); ffma2(a0, q2A[1], k0.y);
        ffma2(a0, q2A[2], k1.x); ffma2(a0, q2A[3], k1.y);
        ffma2(a1, q2A[4], k2.x); ffma2(a1, q2A[5], k2.y);
        ffma2(a1, q2A[6], k3.x); ffma2(a1, q2A[7], k3.y);
        ffma2(b0, q2B[0], k0.x); ffma2(b0, q2B[1], k0.y);
        ffma2(b0, q2B[2], k1.x); ffma2(b0, q2B[3], k1.y);
        ffma2(b1, q2B[4], k2.x); ffma2(b1, q2B[5], k2.y);
        ffma2(b1, q2B[6], k3.x); ffma2(b1, q2B[7], k3.y);
        float lo, hi;
        upk2(a0, lo, hi); p0A[m] = lo + hi;
        upk2(a1, lo, hi); p1A[m] = lo + hi;
        upk2(b0, lo, hi); p0B[m] = lo + hi;
        upk2(b1, lo, hi); p1B[m] = lo + hi;
    }

    // ---- softmax over m, per head, per row (base-2 domain) ----
    {
        float mx0 = p0A[0], mx1 = p1A[0], mx2 = p0B[0], mx3 = p1B[0];
        #pragma unroll
        for (int m = 1; m < 8; m++) {
            mx0 = fmaxf(mx0, p0A[m]); mx1 = fmaxf(mx1, p1A[m]);
            mx2 = fmaxf(mx2, p0B[m]); mx3 = fmaxf(mx3, p1B[m]);
        }
        float s0 = 0.f, s1 = 0.f, s2 = 0.f, s3 = 0.f;
        #pragma unroll
        for (int m = 0; m < 8; m++) {
            p0A[m] = ex2f(p0A[m] - mx0); s0 += p0A[m];
            p1A[m] = ex2f(p1A[m] - mx1); s1 += p1A[m];
            p0B[m] = ex2f(p0B[m] - mx2); s2 += p0B[m];
            p1B[m] = ex2f(p1B[m] - mx3); s3 += p1B[m];
        }
        float i0 = rcpf(s0), i1 = rcpf(s1), i2 = rcpf(s2), i3 = rcpf(s3);
        #pragma unroll
        for (int m = 0; m < 8; m++) {
            p0A[m] *= i0; p1A[m] *= i1; p0B[m] *= i2; p1B[m] *= i3;
        }
    }

    // ---- ctx for both rows; v tiles shared ----
    unsigned long long cxA[8], cxB[8];
    #pragma unroll
    for (int j = 0; j < 8; j++) { cxA[j] = 0ULL; cxB[j] = 0ULL; }
    #pragma unroll
    for (int m = 0; m < 8; m++) {
        int sm = ll * 8 + m;
        int key = SKEY(sm);
        int base = sm * 8;
        ulonglong2 v0 = su[base + (4 ^ key)];
        ulonglong2 v1 = su[base + (5 ^ key)];
        ulonglong2 v2 = su[base + (6 ^ key)];
        ulonglong2 v3 = su[base + (7 ^ key)];
        unsigned long long ppA0 = pk2(p0A[m], p0A[m]);
        unsigned long long ppA1 = pk2(p1A[m], p1A[m]);
        unsigned long long ppB0 = pk2(p0B[m], p0B[m]);
        unsigned long long ppB1 = pk2(p1B[m], p1B[m]);
        ffma2(cxA[0], ppA0, v0.x); ffma2(cxA[1], ppA0, v0.y);
        ffma2(cxA[2], ppA0, v1.x); ffma2(cxA[3], ppA0, v1.y);
        ffma2(cxA[4], ppA1, v2.x); ffma2(cxA[5], ppA1, v2.y);
        ffma2(cxA[6], ppA1, v3.x); ffma2(cxA[7], ppA1, v3.y);
        ffma2(cxB[0], ppB0, v0.x); ffma2(cxB[1], ppB0, v0.y);
        ffma2(cxB[2], ppB0, v1.x); ffma2(cxB[3], ppB0, v1.y);
        ffma2(cxB[4], ppB1, v2.x); ffma2(cxB[5], ppB1, v2.y);
        ffma2(cxB[6], ppB1, v3.x); ffma2(cxB[7], ppB1, v3.y);
    }
    float ceA[16], ceB[16];
    #pragma unroll
    for (int j = 0; j < 8; j++) {
        upk2(cxA[j], ceA[2 * j], ceA[2 * j + 1]);
        upk2(cxB[j], ceB[2 * j], ceB[2 * j + 1]);
    }

    // ---- z = Mt^T ctx, constant port via 128-bit LDCU; bias as accumulator init ----
    const ulonglong2* cMv = reinterpret_cast<const ulonglong2*>(c_pack);
    const unsigned long long* cBu = reinterpret_cast<const unsigned long long*>(c_pack + 512);
    float t[32];
    #pragma unroll
    for (int pass = 0; pass < 2; pass++) {
        unsigned long long zA[8], zB[8];
        #pragma unroll
        for (int j = 0; j < 8; j++) {
            unsigned long long bb = cBu[pass * 8 + j];
            zA[j] = bb; zB[j] = bb;
        }
        #pragma unroll
        for (int e = 0; e < 16; e++) {
            unsigned long long pceA = pk2(ceA[e], ceA[e]);
            unsigned long long pceB = pk2(ceB[e], ceB[e]);
            #pragma unroll
            for (int j4 = 0; j4 < 4; j4++) {
                ulonglong2 wv = cMv[e * 8 + pass * 4 + j4];   // 128-bit constant load
                ffma2(zA[2 * j4], pceA, wv.x);
                ffma2(zA[2 * j4 + 1], pceA, wv.y);
                ffma2(zB[2 * j4], pceB, wv.x);
                ffma2(zB[2 * j4 + 1], pceB, wv.y);
            }
        }
        #pragma unroll
        for (int j = 0; j < 8; j++) {
            float la, ha, lb, hb;
            upk2(zA[j], la, ha);
            upk2(zB[j], lb, hb);
            t[pass * 16 + 2 * j]     = fmaxf(la, 0.f) + fmaxf(lb, 0.f);
            t[pass * 16 + 2 * j + 1] = fmaxf(ha, 0.f) + fmaxf(hb, 0.f);
        }
    }

    // ---- butterfly-sum over the 4 lanes of the loop group; mean ----
    #pragma unroll
    for (int st = 0; st < 2; st++) {
        int mask = 1 << st;
        #pragma unroll
        for (int o = 0; o < 32; o++) t[o] += __shfl_xor_sync(0xffffffffu, t[o], mask);
    }
    unsigned long long t2[16];
    #pragma unroll
    for (int j = 0; j < 16; j++) t2[j] = pk2(t[2 * j] * 0.125f, t[2 * j + 1] * 0.125f);

    // ---- fco: each of 4 lanes computes 8 outputs (packed, swizzled smem) ----
    const ulonglong2* sf = reinterpret_cast<const ulonglong2*>(s_fcw);
    float4 fa = s_fcb4[lj * 2], fb = s_fcb4[lj * 2 + 1];
    float fcb[8] = {fa.x, fa.y, fa.z, fa.w, fb.x, fb.y, fb.z, fb.w};
    float r[8];
    #pragma unroll
    for (int jj = 0; jj < 8; jj++) {
        int o2 = lj * 8 + jj;
        int key = FKEY(o2);
        unsigned long long acc = 0ULL;
        #pragma unroll
        for (int k4 = 0; k4 < 8; k4++) {
            ulonglong2 wv = sf[o2 * 8 + (k4 ^ key)];
            ffma2(acc, t2[2 * k4], wv.x);
            ffma2(acc, t2[2 * k4 + 1], wv.y);
        }
        float lo, hi;
        upk2(acc, lo, hi);
        r[jj] = lo + hi + fcb[jj];
    }

    long long lg = (long long)blockIdx.x * LPB + ll;
    if (lg < B) {
        float4* o4 = reinterpret_cast<float4*>(out);
        o4[lg * 8 + lj * 2]     = make_float4(r[0], r[1], r[2], r[3]);
        o4[lg * 8 + lj * 2 + 1] = make_float4(r[4], r[5], r[6], r[7]);
    }
}

// ---------------- launch ----------------
extern "C" void kernel_launch(void* const* d_in, const int* in_sizes, int n_in,
                              void* d_out, int out_size) {
    const float* node_features = (const float*)d_in[0];
    const void*  stroke_to_loop = d_in[1];
    const float* fc1_w = (const float*)d_in[2];
    const float* fc1_b = (const float*)d_in[3];
    const float* fc2_w = (const float*)d_in[4];
    const float* fc2_b = (const float*)d_in[5];
    const float* in_proj_w = (const float*)d_in[6];
    const float* in_proj_b = (const float*)d_in[7];
    const float* out_proj_w = (const float*)d_in[8];
    const float* out_proj_b = (const float*)d_in[9];
    const float* fc_w = (const float*)d_in[10];
    const float* fc_b = (const float*)d_in[11];
    const float* fco_w = (const float*)d_in[12];
    const float* fco_b = (const float*)d_in[13];

    int N = in_sizes[0] / 6;
    int B = in_sizes[1] / 8;

    cudaFuncSetAttribute(k_loops, cudaFuncAttributeMaxDynamicSharedMemorySize, SMEM_BYTES);

    k_node<<<(N + 255) / 256, 256>>>(node_features, fc1_w, fc1_b, fc2_w, fc2_b,
                                     in_proj_w, in_proj_b,
                                     fc_w, out_proj_w, out_proj_b, fc_b, fco_b,
                                     (const int*)stroke_to_loop, N);

    // single stream-ordered D2D copy of all folded constants
    void* gp = nullptr;
    cudaGetSymbolAddress(&gp, g_cpack);
    cudaMemcpyToSymbolAsync(c_pack, gp, 576 * sizeof(float), 0,
                            cudaMemcpyDeviceToDevice, 0);

    k_loops<<<(B + LPB - 1) / LPB, 128, SMEM_BYTES>>>(stroke_to_loop, fco_w, fco_b,
                                                      (float*)d_out, B);
}

// round 17
// speedup vs baseline: 1.0500x; 1.0058x over previous
#include <cuda_runtime.h>
#include <cstdint>

#define NMAX 100000
#define GREC 12            // float4 chunks per node record (48 floats: q,k,v)
#define LPB  32            // loops per block in k_loops (4 threads per loop)

// dynamic smem partition (float4 units). Warp w's q overlays the FIRST HALF of
// warp w's OWN kv region; indices live in registers (shfl-shared), no idx region.
#define KV_OFF   0                        // 2048 float4 (32 KB)
#define FCW_OFF  (LPB * 8 * 8)            // 256 float4 (4 KB)
#define FCB_OFF  (FCW_OFF + 256)          // 8 float4 (fco bias)
#define SMEM_BYTES ((FCB_OFF + 8) * 16)   // 36992 B -> 6 blocks/SM (with 1KB reserve)

// Scratch (static __device__ — no runtime allocation)
__device__ float4 g_pre[(size_t)NMAX * GREC];   // per-node: q*(invsqrt8*log2e)[16], k[16], v[16]
__device__ float  g_cpack[576];                 // [0:512) Mt[e][o], [512:544) b32, [544:576) fco_b
__device__ int    g_idx64;                      // 1 if stroke_to_loop is int64

// Constant mirror (warp-uniform immediate-indexed reads: uniform/constant port)
__constant__ __align__(16) float c_pack[576];

// k/v chunk swizzle (8 chunks/slot): key distinct across the 8 loop-groups of a warp
#define SKEY(slot) (((slot) ^ ((slot) >> 3)) & 7)
// q chunk swizzle (4 chunks/slot, 64B slot stride): distinct among same-parity slots
#define QKEY(slot) (((slot) >> 1) & 3)
// fco row swizzle: key distinct over the 4 lanes of a loop group
#define FKEY(o) (((o) >> 3) & 3)

__device__ __forceinline__ int fetch_idx(const void* p, long long i, int is64) {
    if (is64) return (int)__ldg((const long long*)p + i);
    return __ldg((const int*)p + i);
}
__device__ __forceinline__ unsigned long long pk2(float lo, float hi) {
    unsigned long long r;
    asm("mov.b64 %0, {%1, %2};" : "=l"(r) : "f"(lo), "f"(hi));
    return r;
}
__device__ __forceinline__ void upk2(unsigned long long v, float& lo, float& hi) {
    asm("mov.b64 {%0, %1}, %2;" : "=f"(lo), "=f"(hi) : "l"(v));
}
__device__ __forceinline__ void ffma2(unsigned long long& d, unsigned long long a, unsigned long long b) {
    asm("fma.rn.f32x2 %0, %1, %2, %0;" : "+l"(d) : "l"(a), "l"(b));
}
__device__ __forceinline__ void cpa16(uint32_t dst_smem, const void* src) {
    asm volatile("cp.async.cg.shared.global [%0], [%1], 16;" :: "r"(dst_smem), "l"(src));
}
__device__ __forceinline__ float ex2f(float x) {
    float r; asm("ex2.approx.f32 %0, %1;" : "=f"(r) : "f"(x)); return r;
}
__device__ __forceinline__ float rcpf(float x) {
    float r; asm("rcp.approx.f32 %0, %1;" : "=f"(r) : "f"(x)); return r;
}

// ---------------- Kernel 1: per-node precompute (+ fused prep in block 0) ----------------
// 256 threads/block: weight staging amortized over 2x nodes vs 128.
__global__ void __launch_bounds__(256)
k_node(const float* __restrict__ nf,
       const float* __restrict__ w1, const float* __restrict__ b1,
       const float* __restrict__ w2, const float* __restrict__ b2,
       const float* __restrict__ wp, const float* __restrict__ bp,
       const float* __restrict__ fc_w, const float* __restrict__ opw,
       const float* __restrict__ opb, const float* __restrict__ fc_b,
       const float* __restrict__ fco_b,
       const int* __restrict__ idx_raw, int N) {
    __shared__ __align__(16) float s_w1[256];    // [32][8] padded rows
    __shared__ __align__(16) float s_w2t[512];   // transposed-interleaved: [j][e]
    __shared__ __align__(16) float s_wpt[768];   // transposed-interleaved: [e][o]
    __shared__ __align__(16) float s_b2[16];
    __shared__ __align__(16) float s_bp[48];
    __shared__ float s_b1[32];
    __shared__ int s_flag;

    const int tid = threadIdx.x;

    if (blockIdx.x == 0) {
        if (tid == 0) s_flag = 0;
        #pragma unroll
        for (int i = tid; i < 512; i += 256) {
            int o = i >> 4, e = i & 15;
            float acc = 0.f;
            #pragma unroll
            for (int j = 0; j < 16; j++) acc += __ldg(fc_w + o * 16 + j) * __ldg(opw + j * 16 + e);
            g_cpack[e * 32 + o] = acc;     // Mt[e][o]
        }
        if (tid < 32) {
            float acc = __ldg(fc_b + tid);
            #pragma unroll
            for (int j = 0; j < 16; j++) acc += __ldg(fc_w + tid * 16 + j) * __ldg(opb + j);
            g_cpack[512 + tid] = acc;
        }
        if (tid >= 32 && tid < 64) g_cpack[544 + (tid - 32)] = __ldg(fco_b + (tid - 32));
        __syncthreads();
        if (tid < 128 && __ldg(idx_raw + 2 * tid + 1) != 0) atomicOr(&s_flag, 1);
        __syncthreads();
        if (tid == 0) g_idx64 = (s_flag == 0) ? 1 : 0;
    }

    // ---- stage weights (transposed-interleaved for packed math) ----
    for (int i = tid; i < 256; i += 256) {
        int o = i >> 3, c = i & 7;
        s_w1[i] = (c < 6) ? __ldg(w1 + o * 6 + c) : 0.f;
    }
    #pragma unroll
    for (int i = tid; i < 512; i += 256) {       // s_w2t[j*16+e] = w2[e*32+j]
        int j = i >> 4, e = i & 15;
        s_w2t[i] = __ldg(w2 + e * 32 + j);
    }
    #pragma unroll
    for (int i = tid; i < 768; i += 256) {       // s_wpt[e*48+o] = wp[o*16+e]
        int e = i / 48, o = i - e * 48;
        s_wpt[i] = __ldg(wp + o * 16 + e);
    }
    if (tid < 32) s_b1[tid] = __ldg(b1 + tid);
    if (tid >= 32 && tid < 48) s_b2[tid - 32] = __ldg(b2 + (tid - 32));
    if (tid >= 64 && tid < 112) s_bp[tid - 64] = __ldg(bp + (tid - 64));
    __syncthreads();

    int n = blockIdx.x * 256 + tid;
    if (n >= N) return;

    float f[6];
    #pragma unroll
    for (int i = 0; i < 6; i++) f[i] = __ldg(nf + (size_t)n * 6 + i);

    const float4* w1v = (const float4*)s_w1;
    float h[32];
    #pragma unroll
    for (int o = 0; o < 32; o++) {
        float4 a = w1v[o * 2], b = w1v[o * 2 + 1];
        float acc = s_b1[o] + a.x * f[0] + a.y * f[1] + a.z * f[2] + a.w * f[3]
                  + b.x * f[4] + b.y * f[5];
        h[o] = fmaxf(acc, 0.f);
    }

    // fc2 packed: X2[p] = (x[2p], x[2p+1])
    const ulonglong2* w2t2 = (const ulonglong2*)s_w2t;
    unsigned long long X2[8];
    {
        const unsigned long long* b2u = (const unsigned long long*)s_b2;
        #pragma unroll
        for (int p = 0; p < 8; p++) X2[p] = b2u[p];
    }
    #pragma unroll
    for (int j = 0; j < 32; j++) {
        unsigned long long hh = pk2(h[j], h[j]);
        #pragma unroll
        for (int t = 0; t < 4; t++) {
            ulonglong2 wv = w2t2[j * 4 + t];
            ffma2(X2[2 * t], hh, wv.x);
            ffma2(X2[2 * t + 1], hh, wv.y);
        }
    }
    float x[16];
    #pragma unroll
    for (int p = 0; p < 8; p++) upk2(X2[p], x[2 * p], x[2 * p + 1]);

    // in_proj packed: Q2[o2] = (qkv[2o2], qkv[2o2+1])
    const ulonglong2* wpt2 = (const ulonglong2*)s_wpt;
    unsigned long long Q2[24];
    {
        const unsigned long long* bpu = (const unsigned long long*)s_bp;
        #pragma unroll
        for (int o2 = 0; o2 < 24; o2++) Q2[o2] = bpu[o2];
    }
    #pragma unroll
    for (int e = 0; e < 16; e++) {
        unsigned long long xx = pk2(x[e], x[e]);
        #pragma unroll
        for (int t = 0; t < 12; t++) {
            ulonglong2 wv = wpt2[e * 12 + t];
            ffma2(Q2[2 * t], xx, wv.x);
            ffma2(Q2[2 * t + 1], xx, wv.y);
        }
    }
    float qkv[48];
    #pragma unroll
    for (int o2 = 0; o2 < 24; o2++) upk2(Q2[o2], qkv[2 * o2], qkv[2 * o2 + 1]);

    float4* rec4 = g_pre + (size_t)n * GREC;
    // 1/sqrt(8) * log2(e): folds score scale AND exp2 conversion into q
    const float s = 0.35355339059327373f * 1.4426950408889634f;
    #pragma unroll
    for (int j = 0; j < 4; j++)
        rec4[j] = make_float4(qkv[4 * j] * s, qkv[4 * j + 1] * s, qkv[4 * j + 2] * s, qkv[4 * j + 3] * s);
    #pragma unroll
    for (int j = 0; j < 8; j++)
        rec4[4 + j] = make_float4(qkv[16 + 4 * j], qkv[17 + 4 * j], qkv[18 + 4 * j], qkv[19 + 4 * j]);
}

// ---------------- Kernel 2: per-loop attention + epilogue ----------------
// 32 loops/block, 4 threads/loop, query rows {lj, lj+4}/thread.
// Warp-local staging; indices register-resident + shfl-shared; q overlays own kv
// region (race-free). smem 36992 B, regs<=85 -> 6 blocks/SM.
__global__ void __launch_bounds__(128, 6)
k_loops(const void* __restrict__ s2l,
        const float* __restrict__ fco_w, const float* __restrict__ fco_b,
        float* __restrict__ out, int B) {
    extern __shared__ __align__(16) float4 smem[];
    float4* s_kv  = smem + KV_OFF;
    float4* s_fcw = smem + FCW_OFF;
    float4* s_fcb4 = smem + FCB_OFF;

    const int tid = threadIdx.x;
    const int wid = tid >> 5;
    const int lane = tid & 31;
    const int wslot0 = wid * 64;               // this warp's first slot
    float4* s_qw = s_kv + wslot0 * 8;          // warp-private q overlay (within OWN kv region)
    const long long base8 = (long long)blockIdx.x * (LPB * 8);
    const long long total8 = (long long)B * 8;
    const int is64 = g_idx64;

    // ---- phase A (block-wide, single barrier): fco weights + bias ----
    const float4* fcw4 = (const float4*)fco_w;
    #pragma unroll
    for (int i = tid; i < 256; i += 128) {
        int r = i >> 3, k4 = i & 7;
        s_fcw[r * 8 + (k4 ^ FKEY(r))] = __ldg(fcw4 + i);
    }
    if (tid < 8) s_fcb4[tid] = __ldg((const float4*)fco_b + tid);
    __syncthreads();

    // ---- indices for this warp's 64 slots: register-resident, shfl-shared ----
    int i0, i1;
    {
        long long gi0 = base8 + wslot0 + lane;      if (gi0 >= total8) gi0 = 0;
        long long gi1 = base8 + wslot0 + 32 + lane; if (gi1 >= total8) gi1 = 0;
        i0 = fetch_idx(s2l, gi0, is64);
        i1 = fetch_idx(s2l, gi1, is64);
    }

    // ---- stage q (coalesced chunk-major cp.async) into WARP-OWN overlay ----
    {
        const int c4 = lane & 3, g4 = lane >> 2;
        #pragma unroll
        for (int it = 0; it < 8; it++) {
            int ls = it * 8 + g4;              // local slot 0..63; half uniform per it
            int node = __shfl_sync(0xffffffffu, (it < 4) ? i0 : i1, (it & 3) * 8 + g4);
            uint32_t dst = (uint32_t)__cvta_generic_to_shared(&s_qw[ls * 4 + (c4 ^ QKEY(ls))]);
            cpa16(dst, g_pre + (size_t)node * GREC + c4);
        }
        asm volatile("cp.async.commit_group;");
        asm volatile("cp.async.wait_group 0;");
    }
    __syncwarp();

    const int ll = tid >> 2;       // loop within block (warp covers 8 loops)
    const int lj = tid & 3;        // lane within loop; query rows lj and lj+4
    const int slotA = ll * 8 + lj;
    const int slotB = slotA + 4;
    const int lsA = slotA & 63;    // local slot within warp
    const int lsB = slotB & 63;

    // ---- read own q rows into registers (conflict-free via QKEY) ----
    unsigned long long q2A[8], q2B[8];
    {
        const ulonglong2* sq = reinterpret_cast<const ulonglong2*>(s_qw);
        int ka = QKEY(lsA);
        #pragma unroll
        for (int j = 0; j < 4; j++) {
            ulonglong2 v = sq[lsA * 4 + (j ^ ka)];
            q2A[2 * j] = v.x; q2A[2 * j + 1] = v.y;
        }
        int kb = QKEY(lsB);
        #pragma unroll
        for (int j = 0; j < 4; j++) {
            ulonglong2 v = sq[lsB * 4 + (j ^ kb)];
            q2B[2 * j] = v.x; q2B[2 * j + 1] = v.y;
        }
    }
    // force all q LDS results into registers before the region is overwritten
    asm volatile("" : "+l"(q2A[0]), "+l"(q2A[1]), "+l"(q2A[2]), "+l"(q2A[3]),
                      "+l"(q2A[4]), "+l"(q2A[5]), "+l"(q2A[6]), "+l"(q2A[7]),
                      "+l"(q2B[0]), "+l"(q2B[1]), "+l"(q2B[2]), "+l"(q2B[3]),
                      "+l"(q2B[4]), "+l"(q2B[5]), "+l"(q2B[6]), "+l"(q2B[7]) :: "memory");
    __syncwarp();

    // ---- stage kv for this warp's 64 slots (overwrites the q overlay safely) ----
    {
        const int c8 = lane & 7, g = lane >> 3;
        #pragma unroll
        for (int it = 0; it < 16; it++) {
            int ls = it * 4 + g;               // local slot; half uniform per it
            int slot = wslot0 + ls;
            int node = __shfl_sync(0xffffffffu, (it < 8) ? i0 : i1, (it & 7) * 4 + g);
            uint32_t dst = (uint32_t)__cvta_generic_to_shared(&s_kv[slot * 8 + (c8 ^ SKEY(slot))]);
            cpa16(dst, g_pre + (size_t)node * GREC + 4 + c8);
        }
        asm volatile("cp.async.commit_group;");
        asm volatile("cp.async.wait_group 0;");
    }
    __syncwarp();

    const ulonglong2* su = reinterpret_cast<const ulonglong2*>(s_kv);

    // ---- scores (log2-scaled; both heads, both rows); k tiles shared across rows ----
    float p0A[8], p1A[8], p0B[8], p1B[8];
    #pragma unroll
    for (int m = 0; m < 8; m++) {
        int sm = ll * 8 + m;
        int key = SKEY(sm);
        int base = sm * 8;
        ulonglong2 k0 = su[base + (0 ^ key)];
        ulonglong2 k1 = su[base + (1 ^ key)];
        ulonglong2 k2 = su[base + (2 ^ key)];
        ulonglong2 k3 = su[base + (3 ^ key)];
        unsigned long long a0 = 0ULL, a1 = 0ULL, b0 = 0ULL, b1 = 0ULL;
        ffma2(a0, q2A[0], k0.x); ffma2(a0, q2A[1], k0.y);
        ffma2(a0, q2A[2], k1.x); ffma2(a0, q2A[3], k1.y);
        ffma2(a1, q2A[4], k2.x); ffma2(a1, q2A[5], k2.y);
        ffma2(a1, q2A[6], k3.x); ffma2(a1, q2A[7], k3.y);
        ffma2(b0, q2B[0], k0.x); ffma2(b0, q2B[1], k0.y);
        ffma2(b0, q2B[2], k1.x); ffma2(b0, q2B[3], k1.y);
        ffma2(b1, q2B[4], k2.x); ffma2(b1, q2B[5], k2.y);
        ffma2(b1, q2B[6], k3.x); ffma2(b1, q2B[7], k3.y);
        float lo, hi;
        upk2(a0, lo, hi); p0A[m] = lo + hi;
        upk2(a1, lo, hi); p1A[m] = lo + hi;
        upk2(b0, lo, hi); p0B[m] = lo + hi;
        upk2(b1, lo, hi); p1B[m] = lo + hi;
    }

    // ---- softmax over m, per head, per row (base-2 domain) ----
    {
        float mx0 = p0A[0], mx1 = p1A[0], mx2 = p0B[0], mx3 = p1B[0];
        #pragma unroll
        for (int m = 1; m < 8; m++) {
            mx0 = fmaxf(mx0, p0A[m]); mx1 = fmaxf(mx1, p1A[m]);
            mx2 = fmaxf(mx2, p0B[m]); mx3 = fmaxf(mx3, p1B[m]);
        }
        float s0 = 0.f, s1 = 0.f, s2 = 0.f, s3 = 0.f;
        #pragma unroll
        for (int m = 0; m < 8; m++) {
            p0A[m] = ex2f(p0A[m] - mx0); s0 += p0A[m];
            p1A[m] = ex2f(p1A[m] - mx1); s1 += p1A[m];
            p0B[m] = ex2f(p0B[m] - mx2); s2 += p0B[m];
            p1B[m] = ex2f(p1B[m] - mx3); s3 += p1B[m];
        }
        float i0f = rcpf(s0), i1f = rcpf(s1), i2f = rcpf(s2), i3f = rcpf(s3);
        #pragma unroll
        for (int m = 0; m < 8; m++) {
            p0A[m] *= i0f; p1A[m] *= i1f; p0B[m] *= i2f; p1B[m] *= i3f;
        }
    }

    // ---- ctx for both rows; v tiles shared ----
    unsigned long long cxA[8], cxB[8];
    #pragma unroll
    for (int j = 0; j < 8; j++) { cxA[j] = 0ULL; cxB[j] = 0ULL; }
    #pragma unroll
    for (int m = 0; m < 8; m++) {
        int sm = ll * 8 + m;
        int key = SKEY(sm);
        int base = sm * 8;
        ulonglong2 v0 = su[base + (4 ^ key)];
        ulonglong2 v1 = su[base + (5 ^ key)];
        ulonglong2 v2 = su[base + (6 ^ key)];
        ulonglong2 v3 = su[base + (7 ^ key)];
        unsigned long long ppA0 = pk2(p0A[m], p0A[m]);
        unsigned long long ppA1 = pk2(p1A[m], p1A[m]);
        unsigned long long ppB0 = pk2(p0B[m], p0B[m]);
        unsigned long long ppB1 = pk2(p1B[m], p1B[m]);
        ffma2(cxA[0], ppA0, v0.x); ffma2(cxA[1], ppA0, v0.y);
        ffma2(cxA[2], ppA0, v1.x); ffma2(cxA[3], ppA0, v1.y);
        ffma2(cxA[4], ppA1, v2.x); ffma2(cxA[5], ppA1, v2.y);
        ffma2(cxA[6], ppA1, v3.x); ffma2(cxA[7], ppA1, v3.y);
        ffma2(cxB[0], ppB0, v0.x); ffma2(cxB[1], ppB0, v0.y);
        ffma2(cxB[2], ppB0, v1.x); ffma2(cxB[3], ppB0, v1.y);
        ffma2(cxB[4], ppB1, v2.x); ffma2(cxB[5], ppB1, v2.y);
        ffma2(cxB[6], ppB1, v3.x); ffma2(cxB[7], ppB1, v3.y);
    }
    float ceA[16], ceB[16];
    #pragma unroll
    for (int j = 0; j < 8; j++) {
        upk2(cxA[j], ceA[2 * j], ceA[2 * j + 1]);
        upk2(cxB[j], ceB[2 * j], ceB[2 * j + 1]);
    }

    // ---- z = Mt^T ctx, constant port via 128-bit LDCU; bias as accumulator init ----
    const ulonglong2* cMv = reinterpret_cast<const ulonglong2*>(c_pack);
    const unsigned long long* cBu = reinterpret_cast<const unsigned long long*>(c_pack + 512);
    float t[32];
    #pragma unroll
    for (int pass = 0; pass < 2; pass++) {
        unsigned long long zA[8], zB[8];
        #pragma unroll
        for (int j = 0; j < 8; j++) {
            unsigned long long bb = cBu[pass * 8 + j];
            zA[j] = bb; zB[j] = bb;
        }
        #pragma unroll
        for (int e = 0; e < 16; e++) {
            unsigned long long pceA = pk2(ceA[e], ceA[e]);
            unsigned long long pceB = pk2(ceB[e], ceB[e]);
            #pragma unroll
            for (int j4 = 0; j4 < 4; j4++) {
                ulonglong2 wv = cMv[e * 8 + pass * 4 + j4];   // 128-bit constant load
                ffma2(zA[2 * j4], pceA, wv.x);
                ffma2(zA[2 * j4 + 1], pceA, wv.y);
                ffma2(zB[2 * j4], pceB, wv.x);
                ffma2(zB[2 * j4 + 1], pceB, wv.y);
            }
        }
        #pragma unroll
        for (int j = 0; j < 8; j++) {
            float la, ha, lb, hb;
            upk2(zA[j], la, ha);
            upk2(zB[j], lb, hb);
            t[pass * 16 + 2 * j]     = fmaxf(la, 0.f) + fmaxf(lb, 0.f);
            t[pass * 16 + 2 * j + 1] = fmaxf(ha, 0.f) + fmaxf(hb, 0.f);
        }
    }

    // ---- butterfly-sum over the 4 lanes of the loop group; mean ----
    #pragma unroll
    for (int st = 0; st < 2; st++) {
        int mask = 1 << st;
        #pragma unroll
        for (int o = 0; o < 32; o++) t[o] += __shfl_xor_sync(0xffffffffu, t[o], mask);
    }
    unsigned long long t2[16];
    #pragma unroll
    for (int j = 0; j < 16; j++) t2[j] = pk2(t[2 * j] * 0.125f, t[2 * j + 1] * 0.125f);

    // ---- fco: each of 4 lanes computes 8 outputs (packed, swizzled smem) ----
    const ulonglong2* sf = reinterpret_cast<const ulonglong2*>(s_fcw);
    float4 fa = s_fcb4[lj * 2], fb = s_fcb4[lj * 2 + 1];
    float fcb[8] = {fa.x, fa.y, fa.z, fa.w, fb.x, fb.y, fb.z, fb.w};
    float r[8];
    #pragma unroll
    for (int jj = 0; jj < 8; jj++) {
        int o2 = lj * 8 + jj;
        int key = FKEY(o2);
        unsigned long long acc = 0ULL;
        #pragma unroll
        for (int k4 = 0; k4 < 8; k4++) {
            ulonglong2 wv = sf[o2 * 8 + (k4 ^ key)];
            ffma2(acc, t2[2 * k4], wv.x);
            ffma2(acc, t2[2 * k4 + 1], wv.y);
        }
        float lo, hi;
        upk2(acc, lo, hi);
        r[jj] = lo + hi + fcb[jj];
    }

    long long lg = (long long)blockIdx.x * LPB + ll;
    if (lg < B) {
        float4* o4 = reinterpret_cast<float4*>(out);
        o4[lg * 8 + lj * 2]     = make_float4(r[0], r[1], r[2], r[3]);
        o4[lg * 8 + lj * 2 + 1] = make_float4(r[4], r[5], r[6], r[7]);
    }
}

// ---------------- launch ----------------
extern "C" void kernel_launch(void* const* d_in, const int* in_sizes, int n_in,
                              void* d_out, int out_size) {
    const float* node_features = (const float*)d_in[0];
    const void*  stroke_to_loop = d_in[1];
    const float* fc1_w = (const float*)d_in[2];
    const float* fc1_b = (const float*)d_in[3];
    const float* fc2_w = (const float*)d_in[4];
    const float* fc2_b = (const float*)d_in[5];
    const float* in_proj_w = (const float*)d_in[6];
    const float* in_proj_b = (const float*)d_in[7];
    const float* out_proj_w = (const float*)d_in[8];
    const float* out_proj_b = (const float*)d_in[9];
    const float* fc_w = (const float*)d_in[10];
    const float* fc_b = (const float*)d_in[11];
    const float* fco_w = (const float*)d_in[12];
    const float* fco_b = (const float*)d_in[13];

    int N = in_sizes[0] / 6;
    int B = in_sizes[1] / 8;

    cudaFuncSetAttribute(k_loops, cudaFuncAttributeMaxDynamicSharedMemorySize, SMEM_BYTES);

    k_node<<<(N + 255) / 256, 256>>>(node_features, fc1_w, fc1_b, fc2_w, fc2_b,
                                     in_proj_w, in_proj_b,
                                     fc_w, out_proj_w, out_proj_b, fc_b, fco_b,
                                     (const int*)stroke_to_loop, N);

    // single stream-ordered D2D copy of all folded constants
    void* gp = nullptr;
    cudaGetSymbolAddress(&gp, g_cpack);
    cudaMemcpyToSymbolAsync(c_pack, gp, 576 * sizeof(float), 0,
                            cudaMemcpyDeviceToDevice, 0);

    k_loops<<<(B + LPB - 1) / LPB, 128, SMEM_BYTES>>>(stroke_to_loop, fco_w, fco_b,
                                                      (float*)d_out, B);
}